// round 8
// baseline (speedup 1.0000x reference)
#include <cuda_runtime.h>
#include <mma.h>
#include <cstdint>
using namespace nvcuda;

#define SEQ 2048
#define CD  1024
#define NQ  3072
#define RWS 8192
#define BR  4096

// scratch (device globals; allocation forbidden)
__device__ float g_QKVf[(size_t)RWS * NQ];   // [row, 3C]
__device__ float g_O[(size_t)RWS * CD];      // attention out

__device__ __forceinline__ uint32_t smem_u32(const void* p) {
    uint32_t a;
    asm("{ .reg .u64 t; cvta.to.shared.u64 t, %1; cvt.u32.u64 %0, t; }" : "=r"(a) : "l"(p));
    return a;
}
__device__ __forceinline__ float ex2(float x) {
    float r; asm("ex2.approx.f32 %0, %1;" : "=f"(r) : "f"(x)); return r;
}
#define CPA16(dst, src) \
    asm volatile("cp.async.cg.shared.global [%0], [%1], 16;" :: "r"(dst), "l"(src) : "memory")
#define CP_COMMIT() asm volatile("cp.async.commit_group;" ::: "memory")

template<class F>
__device__ __forceinline__ void cvt_tf32(F& f) {
    #pragma unroll
    for (int i = 0; i < f.num_elements; i++) f.x[i] = wmma::__float_to_tf32(f.x[i]);
}

typedef wmma::fragment<wmma::matrix_a, 16, 16, 8, wmma::precision::tf32, wmma::row_major> FragA;
typedef wmma::fragment<wmma::matrix_b, 16, 16, 8, wmma::precision::tf32, wmma::row_major> FragB;
typedef wmma::fragment<wmma::matrix_b, 16, 16, 8, wmma::precision::tf32, wmma::col_major> FragBT;
typedef wmma::fragment<wmma::accumulator, 16, 16, 8, float> FragC;

// ---------------------------------------------------------------------------
// GEMM: C[8192, N] = A[8192,1024] @ W[1024,N]   (identical to the passing R5)
// SEL 0: A = concat(x,y), W = w_qkv (N=3072), C -> g_QKVf
// SEL 1: A = g_O,         W = w_proj (N=1024), C -> out (+bias+residual)
// ---------------------------------------------------------------------------
#define GEMM_SMEM_BYTES 75776
template<int SEL>
__global__ __launch_bounds__(128) void gemm_tc(const float* __restrict__ x,
                                               const float* __restrict__ y,
                                               const float* __restrict__ W,
                                               const float* __restrict__ bias,
                                               float* __restrict__ out) {
    extern __shared__ float sh[];
    const int N = SEL ? CD : NQ;
    const int tid = threadIdx.x, wid = tid >> 5;
    const int bm = blockIdx.y * 128, bn = blockIdx.x * 128;
    const int wr = (wid & 1) * 64, wc = (wid >> 1) * 64;
    const uint32_t sb = smem_u32(sh);

    FragC acc[4][4];
    #pragma unroll
    for (int i = 0; i < 4; i++)
        #pragma unroll
        for (int j = 0; j < 4; j++) wmma::fill_fragment(acc[i][j], 0.f);

    auto issue = [&](int c) {
        int k0 = c * 32;
        uint32_t ab = (uint32_t)(c & 1) * 5120u, bb = 10240u + (uint32_t)(c & 1) * 4352u;
        #pragma unroll
        for (int j = 0; j < 8; j++) {
            int u = tid + j * 128;
            int row = u >> 3, c4 = (u & 7) * 4;
            const float* src;
            int grow = bm + row;
            if (SEL == 0)
                src = ((grow < BR) ? x + (size_t)grow * CD
                                   : y + (size_t)(grow - BR) * CD) + k0 + c4;
            else
                src = g_O + (size_t)grow * CD + k0 + c4;
            CPA16(sb + (ab + (uint32_t)(row * 40 + c4)) * 4u, src);
        }
        #pragma unroll
        for (int j = 0; j < 8; j++) {
            int u = tid + j * 128;
            int row = u >> 5, c4 = (u & 31) * 4;
            CPA16(sb + (bb + (uint32_t)(row * 136 + c4)) * 4u,
                  W + (size_t)(k0 + row) * N + bn + c4);
        }
        CP_COMMIT();
    };

    issue(0);
    for (int c = 0; c < 32; c++) {
        if (c < 31) { issue(c + 1); asm volatile("cp.async.wait_group 1;" ::: "memory"); }
        else        {               asm volatile("cp.async.wait_group 0;" ::: "memory"); }
        __syncthreads();
        const float* A0 = sh + (c & 1) * 5120;
        const float* B0 = sh + 10240 + (c & 1) * 4352;
        #pragma unroll
        for (int s = 0; s < 4; s++) {
            FragA a[4]; FragB b[4];
            #pragma unroll
            for (int i = 0; i < 4; i++) {
                wmma::load_matrix_sync(a[i], A0 + (wr + i * 16) * 40 + s * 8, 40);
                cvt_tf32(a[i]);
            }
            #pragma unroll
            for (int j = 0; j < 4; j++) {
                wmma::load_matrix_sync(b[j], B0 + (s * 8) * 136 + wc + j * 16, 136);
                cvt_tf32(b[j]);
            }
            #pragma unroll
            for (int i = 0; i < 4; i++)
                #pragma unroll
                for (int j = 0; j < 4; j++)
                    wmma::mma_sync(acc[i][j], a[i], b[j], acc[i][j]);
        }
        __syncthreads();
    }

    if (SEL == 0) {
        #pragma unroll
        for (int i = 0; i < 4; i++)
            #pragma unroll
            for (int j = 0; j < 4; j++)
                wmma::store_matrix_sync(
                    g_QKVf + (size_t)(bm + wr + i * 16) * N + bn + wc + j * 16,
                    acc[i][j], N, wmma::mem_row_major);
    } else {
        #pragma unroll
        for (int i = 0; i < 4; i++)
            #pragma unroll
            for (int j = 0; j < 4; j++)
                wmma::store_matrix_sync(sh + (wr + i * 16) * 136 + wc + j * 16,
                                        acc[i][j], 136, wmma::mem_row_major);
        __syncthreads();
        #pragma unroll
        for (int j = 0; j < 32; j++) {
            int u = tid + j * 128;
            int row = u >> 5, c4 = (u & 31) * 4;
            int grow = bm + row;
            const float* res = ((grow < BR) ? x + (size_t)grow * CD
                                            : y + (size_t)(grow - BR) * CD) + bn + c4;
            float4 cv = *(float4*)(sh + row * 136 + c4);
            float4 bv = *(const float4*)(bias + bn + c4);
            float4 rv = *(const float4*)res;
            cv.x += bv.x + rv.x; cv.y += bv.y + rv.y;
            cv.z += bv.z + rv.z; cv.w += bv.w + rv.w;
            *(float4*)(out + (size_t)grow * CD + bn + c4) = cv;
        }
    }
}

// ---------------------------------------------------------------------------
// Flash attention, tf32 wmma, max-free exp2 softmax — R5 math, now with
// DOUBLE-BUFFERED K/V cp.async (load kt+1 overlaps compute kt).
// grid (16 q-tiles of 128, 64 jobs), 256 thr (8 warps).
// smem floats: KV buf b at b*9216 (K 64x72, then V 64x72),
//              Ss f32[128][72] @ 18432, rs[256] @ 27648  => 111616 B
// ---------------------------------------------------------------------------
#define ATT_SMEM_BYTES 111616
__global__ __launch_bounds__(256) void attn_tc() {
    extern __shared__ float sh[];
    float* Ss = sh + 18432;
    float* rs = sh + 27648;
    const uint32_t sb = smem_u32(sh);

    const int tid = threadIdx.x, wid = tid >> 5;
    const int job = blockIdx.y;
    const int p = job >> 5, b = (job >> 4) & 1, h = job & 15;
    const int q0 = blockIdx.x * 128;
    const size_t base  = (size_t)(p * 2 + b) * SEQ * NQ;
    const size_t baseV = (size_t)((1 - p) * 2 + b) * SEQ * NQ;
    const float* qp = g_QKVf + base + (size_t)h * 64;
    const float* kp = g_QKVf + base + CD + (size_t)h * 64;
    const float* vp = g_QKVf + baseV + 2 * CD + (size_t)h * 64;

    // Q a-fragments live in registers for the whole kv loop
    FragA qa[8];
    #pragma unroll
    for (int s = 0; s < 8; s++) {
        wmma::load_matrix_sync(qa[s], qp + (size_t)(q0 + wid * 16) * NQ + s * 8, NQ);
        cvt_tf32(qa[s]);
    }
    FragC oacc[4];
    #pragma unroll
    for (int j = 0; j < 4; j++) wmma::fill_fragment(oacc[j], 0.f);

    float lsum = 0.f;
    const float SC = 0.18033688f;   // D^-0.5 * log2(e)

    auto issueKV = [&](int kt) {
        uint32_t boff = (uint32_t)(kt & 1) * 9216u;
        #pragma unroll
        for (int j = 0; j < 4; j++) {
            int u = tid + j * 256;
            int row = u >> 4, c4 = (u & 15) * 4;
            size_t go = (size_t)(kt * 64 + row) * NQ + c4;
            CPA16(sb + (boff + (uint32_t)(row * 72 + c4)) * 4u, kp + go);
            CPA16(sb + (boff + 4608u + (uint32_t)(row * 72 + c4)) * 4u, vp + go);
        }
        CP_COMMIT();
    };

    issueKV(0);
    for (int kt = 0; kt < 32; kt++) {
        if (kt < 31) { issueKV(kt + 1); asm volatile("cp.async.wait_group 1;" ::: "memory"); }
        else         {                  asm volatile("cp.async.wait_group 0;" ::: "memory"); }
        __syncthreads();
        const float* Ks = sh + (kt & 1) * 9216;
        const float* Vs = Ks + 4608;

        // S = Q @ K^T
        FragC c[4];
        #pragma unroll
        for (int j = 0; j < 4; j++) wmma::fill_fragment(c[j], 0.f);
        #pragma unroll
        for (int s = 0; s < 8; s++) {
            #pragma unroll
            for (int j = 0; j < 4; j++) {
                FragBT kb;
                wmma::load_matrix_sync(kb, Ks + (j * 16) * 72 + s * 8, 72);
                cvt_tf32(kb);
                wmma::mma_sync(c[j], qa[s], kb, c[j]);
            }
        }
        #pragma unroll
        for (int j = 0; j < 4; j++)
            wmma::store_matrix_sync(Ss + (wid * 16) * 72 + j * 16, c[j], 72,
                                    wmma::mem_row_major);
        __syncthreads();

        // softmax (max-free): P = exp2(S * SC)
        {
            float* pr = Ss + (tid >> 1) * 72 + (tid & 1) * 32;
            #pragma unroll
            for (int q = 0; q < 8; q++) {
                float4 v = *(float4*)(pr + q * 4);
                v.x = ex2(v.x * SC); v.y = ex2(v.y * SC);
                v.z = ex2(v.z * SC); v.w = ex2(v.w * SC);
                lsum += v.x + v.y + v.z + v.w;
                *(float4*)(pr + q * 4) = v;
            }
        }
        __syncthreads();

        // O += P @ V
        #pragma unroll
        for (int s = 0; s < 8; s++) {
            FragA pa;
            wmma::load_matrix_sync(pa, Ss + (wid * 16) * 72 + s * 8, 72);
            cvt_tf32(pa);
            #pragma unroll
            for (int j = 0; j < 4; j++) {
                FragB vb;
                wmma::load_matrix_sync(vb, Vs + (s * 8) * 72 + j * 16, 72);
                cvt_tf32(vb);
                wmma::mma_sync(oacc[j], pa, vb, oacc[j]);
            }
        }
        __syncthreads();   // protect Ss and KV buf (kt&1) before reuse
    }

    rs[tid] = lsum;
    __syncthreads();
    #pragma unroll
    for (int j = 0; j < 4; j++)
        wmma::store_matrix_sync(Ss + (wid * 16) * 72 + j * 16, oacc[j], 72,
                                wmma::mem_row_major);
    __syncthreads();
    {
        int row = tid >> 1;
        float inv = 1.f / (rs[row * 2] + rs[row * 2 + 1]);
        float* pr = Ss + row * 72 + (tid & 1) * 32;
        float* op = g_O + ((size_t)(p * 2 + b) * SEQ + q0 + row) * CD
                  + (size_t)h * 64 + (tid & 1) * 32;
        #pragma unroll
        for (int q = 0; q < 8; q++) {
            float4 v = *(float4*)(pr + q * 4);
            v.x *= inv; v.y *= inv; v.z *= inv; v.w *= inv;
            *(float4*)(op + q * 4) = v;
        }
    }
}

// ---------------------------------------------------------------------------
extern "C" void kernel_launch(void* const* d_in, const int* in_sizes, int n_in,
                              void* d_out, int out_size) {
    const float* x      = (const float*)d_in[0];
    const float* y      = (const float*)d_in[1];
    const float* w_qkv  = (const float*)d_in[2];
    const float* w_proj = (const float*)d_in[3];
    const float* b_proj = (const float*)d_in[4];
    float* out = (float*)d_out;

    cudaFuncSetAttribute(gemm_tc<0>, cudaFuncAttributeMaxDynamicSharedMemorySize, GEMM_SMEM_BYTES);
    cudaFuncSetAttribute(gemm_tc<1>, cudaFuncAttributeMaxDynamicSharedMemorySize, GEMM_SMEM_BYTES);
    cudaFuncSetAttribute(attn_tc,    cudaFuncAttributeMaxDynamicSharedMemorySize, ATT_SMEM_BYTES);

    gemm_tc<0><<<dim3(NQ / 128, RWS / 128), 128, GEMM_SMEM_BYTES>>>(x, y, w_qkv, nullptr, nullptr);
    attn_tc<<<dim3(SEQ / 128, 64), 256, ATT_SMEM_BYTES>>>();
    gemm_tc<1><<<dim3(CD / 128, RWS / 128), 128, GEMM_SMEM_BYTES>>>(x, y, w_proj, b_proj, out);
}

// round 9
// speedup vs baseline: 1.0458x; 1.0458x over previous
#include <cuda_runtime.h>
#include <mma.h>
#include <cstdint>
using namespace nvcuda;

#define SEQ 2048
#define CD  1024
#define NQ  3072
#define RWS 8192
#define BR  4096

// scratch (device globals; allocation forbidden)
__device__ float g_QKVf[(size_t)RWS * NQ];   // [row, 3C]
__device__ float g_O[(size_t)RWS * CD];      // attention out

__device__ __forceinline__ uint32_t smem_u32(const void* p) {
    uint32_t a;
    asm("{ .reg .u64 t; cvta.to.shared.u64 t, %1; cvt.u32.u64 %0, t; }" : "=r"(a) : "l"(p));
    return a;
}
__device__ __forceinline__ float ex2(float x) {
    float r; asm("ex2.approx.f32 %0, %1;" : "=f"(r) : "f"(x)); return r;
}
#define CPA16(dst, src) \
    asm volatile("cp.async.cg.shared.global [%0], [%1], 16;" :: "r"(dst), "l"(src) : "memory")
#define CP_COMMIT() asm volatile("cp.async.commit_group;" ::: "memory")

template<class F>
__device__ __forceinline__ void cvt_tf32(F& f) {
    #pragma unroll
    for (int i = 0; i < f.num_elements; i++) f.x[i] = wmma::__float_to_tf32(f.x[i]);
}

typedef wmma::fragment<wmma::matrix_a, 16, 16, 8, wmma::precision::tf32, wmma::row_major> FragA;
typedef wmma::fragment<wmma::matrix_b, 16, 16, 8, wmma::precision::tf32, wmma::row_major> FragB;
typedef wmma::fragment<wmma::matrix_b, 16, 16, 8, wmma::precision::tf32, wmma::col_major> FragBT;
typedef wmma::fragment<wmma::accumulator, 16, 16, 8, float> FragC;

// ---------------------------------------------------------------------------
// GEMM: C[8192, N] = A[8192,1024] @ W[1024,N]
// 256 thr (8 warps, 2x4 layout, 64x32 warp tile), BK=32, double-buffered.
// SEL 0: A = concat(x,y), W = w_qkv (N=3072), C -> g_QKVf
// SEL 1: A = g_O,         W = w_proj (N=1024), C -> out (+bias+residual)
// smem floats: A buf b at b*5120 (128x40), B buf b at 10240+b*4352 (32x136)
// ---------------------------------------------------------------------------
#define GEMM_SMEM_BYTES 75776
template<int SEL>
__global__ __launch_bounds__(256, 2) void gemm_tc(const float* __restrict__ x,
                                                  const float* __restrict__ y,
                                                  const float* __restrict__ W,
                                                  const float* __restrict__ bias,
                                                  float* __restrict__ out) {
    extern __shared__ float sh[];
    const int N = SEL ? CD : NQ;
    const int tid = threadIdx.x, wid = tid >> 5;
    const int bm = blockIdx.y * 128, bn = blockIdx.x * 128;
    const int wr = (wid & 1) * 64;        // warp row (2 rows of 64)
    const int wc = (wid >> 1) * 32;       // warp col (4 cols of 32)
    const uint32_t sb = smem_u32(sh);

    FragC acc[4][2];
    #pragma unroll
    for (int i = 0; i < 4; i++)
        #pragma unroll
        for (int j = 0; j < 2; j++) wmma::fill_fragment(acc[i][j], 0.f);

    auto issue = [&](int c) {
        int k0 = c * 32;
        uint32_t ab = (uint32_t)(c & 1) * 5120u, bb = 10240u + (uint32_t)(c & 1) * 4352u;
        #pragma unroll
        for (int j = 0; j < 4; j++) {          // A: 1024 f4 units
            int u = tid + j * 256;
            int row = u >> 3, c4 = (u & 7) * 4;
            const float* src;
            int grow = bm + row;
            if (SEL == 0)
                src = ((grow < BR) ? x + (size_t)grow * CD
                                   : y + (size_t)(grow - BR) * CD) + k0 + c4;
            else
                src = g_O + (size_t)grow * CD + k0 + c4;
            CPA16(sb + (ab + (uint32_t)(row * 40 + c4)) * 4u, src);
        }
        #pragma unroll
        for (int j = 0; j < 4; j++) {          // B: 1024 f4 units
            int u = tid + j * 256;
            int row = u >> 5, c4 = (u & 31) * 4;
            CPA16(sb + (bb + (uint32_t)(row * 136 + c4)) * 4u,
                  W + (size_t)(k0 + row) * N + bn + c4);
        }
        CP_COMMIT();
    };

    issue(0);
    for (int c = 0; c < 32; c++) {
        if (c < 31) { issue(c + 1); asm volatile("cp.async.wait_group 1;" ::: "memory"); }
        else        {               asm volatile("cp.async.wait_group 0;" ::: "memory"); }
        __syncthreads();
        const float* A0 = sh + (c & 1) * 5120;
        const float* B0 = sh + 10240 + (c & 1) * 4352;
        #pragma unroll
        for (int s = 0; s < 4; s++) {
            FragA a[4]; FragB b[2];
            #pragma unroll
            for (int i = 0; i < 4; i++) {
                wmma::load_matrix_sync(a[i], A0 + (wr + i * 16) * 40 + s * 8, 40);
                cvt_tf32(a[i]);
            }
            #pragma unroll
            for (int j = 0; j < 2; j++) {
                wmma::load_matrix_sync(b[j], B0 + (s * 8) * 136 + wc + j * 16, 136);
                cvt_tf32(b[j]);
            }
            #pragma unroll
            for (int i = 0; i < 4; i++)
                #pragma unroll
                for (int j = 0; j < 2; j++)
                    wmma::mma_sync(acc[i][j], a[i], b[j], acc[i][j]);
        }
        __syncthreads();
    }

    if (SEL == 0) {
        #pragma unroll
        for (int i = 0; i < 4; i++)
            #pragma unroll
            for (int j = 0; j < 2; j++)
                wmma::store_matrix_sync(
                    g_QKVf + (size_t)(bm + wr + i * 16) * N + bn + wc + j * 16,
                    acc[i][j], N, wmma::mem_row_major);
    } else {
        // stage C in smem (128 x 136), then + bias + residual -> out
        #pragma unroll
        for (int i = 0; i < 4; i++)
            #pragma unroll
            for (int j = 0; j < 2; j++)
                wmma::store_matrix_sync(sh + (wr + i * 16) * 136 + wc + j * 16,
                                        acc[i][j], 136, wmma::mem_row_major);
        __syncthreads();
        #pragma unroll
        for (int j = 0; j < 16; j++) {
            int u = tid + j * 256;          // f4 unit, 0..4095
            int row = u >> 5, c4 = (u & 31) * 4;
            int grow = bm + row;
            const float* res = ((grow < BR) ? x + (size_t)grow * CD
                                            : y + (size_t)(grow - BR) * CD) + bn + c4;
            float4 cv = *(float4*)(sh + row * 136 + c4);
            float4 bv = *(const float4*)(bias + bn + c4);
            float4 rv = *(const float4*)res;
            cv.x += bv.x + rv.x; cv.y += bv.y + rv.y;
            cv.z += bv.z + rv.z; cv.w += bv.w + rv.w;
            *(float4*)(out + (size_t)grow * CD + bn + c4) = cv;
        }
    }
}

// ---------------------------------------------------------------------------
// Flash attention, tf32 wmma, max-free exp2 softmax — exact R5 version
// (single-buffered K/V, 74752 B smem -> 2 CTAs/SM).
// grid (16 q-tiles of 128, 64 jobs), 256 thr (8 warps).
// smem floats: Ks[64][72]@0, Vs[64][72]@4608, Ss[128][72]@9216, rs[256]@18432
// ---------------------------------------------------------------------------
#define ATT_SMEM_BYTES 74752
__global__ __launch_bounds__(256) void attn_tc() {
    extern __shared__ float sh[];
    float* Ks = sh;
    float* Vs = sh + 4608;
    float* Ss = sh + 9216;
    float* rs = sh + 18432;
    const uint32_t sb = smem_u32(sh);

    const int tid = threadIdx.x, wid = tid >> 5;
    const int job = blockIdx.y;
    const int p = job >> 5, b = (job >> 4) & 1, h = job & 15;
    const int q0 = blockIdx.x * 128;
    const size_t base  = (size_t)(p * 2 + b) * SEQ * NQ;
    const size_t baseV = (size_t)((1 - p) * 2 + b) * SEQ * NQ;
    const float* qp = g_QKVf + base + (size_t)h * 64;
    const float* kp = g_QKVf + base + CD + (size_t)h * 64;
    const float* vp = g_QKVf + baseV + 2 * CD + (size_t)h * 64;

    FragA qa[8];
    #pragma unroll
    for (int s = 0; s < 8; s++) {
        wmma::load_matrix_sync(qa[s], qp + (size_t)(q0 + wid * 16) * NQ + s * 8, NQ);
        cvt_tf32(qa[s]);
    }
    FragC oacc[4];
    #pragma unroll
    for (int j = 0; j < 4; j++) wmma::fill_fragment(oacc[j], 0.f);

    float lsum = 0.f;
    const float SC = 0.18033688f;   // D^-0.5 * log2(e)

    for (int kt = 0; kt < 32; kt++) {
        #pragma unroll
        for (int j = 0; j < 4; j++) {
            int u = tid + j * 256;
            int row = u >> 4, c4 = (u & 15) * 4;
            size_t go = (size_t)(kt * 64 + row) * NQ + c4;
            CPA16(sb + (uint32_t)(row * 72 + c4) * 4u, kp + go);
            CPA16(sb + (uint32_t)(4608 + row * 72 + c4) * 4u, vp + go);
        }
        CP_COMMIT();
        asm volatile("cp.async.wait_group 0;" ::: "memory");
        __syncthreads();

        // S = Q @ K^T
        FragC c[4];
        #pragma unroll
        for (int j = 0; j < 4; j++) wmma::fill_fragment(c[j], 0.f);
        #pragma unroll
        for (int s = 0; s < 8; s++) {
            #pragma unroll
            for (int j = 0; j < 4; j++) {
                FragBT kb;
                wmma::load_matrix_sync(kb, Ks + (j * 16) * 72 + s * 8, 72);
                cvt_tf32(kb);
                wmma::mma_sync(c[j], qa[s], kb, c[j]);
            }
        }
        #pragma unroll
        for (int j = 0; j < 4; j++)
            wmma::store_matrix_sync(Ss + (wid * 16) * 72 + j * 16, c[j], 72,
                                    wmma::mem_row_major);
        __syncthreads();

        // softmax (max-free): P = exp2(S * SC)
        {
            float* pr = Ss + (tid >> 1) * 72 + (tid & 1) * 32;
            #pragma unroll
            for (int q = 0; q < 8; q++) {
                float4 v = *(float4*)(pr + q * 4);
                v.x = ex2(v.x * SC); v.y = ex2(v.y * SC);
                v.z = ex2(v.z * SC); v.w = ex2(v.w * SC);
                lsum += v.x + v.y + v.z + v.w;
                *(float4*)(pr + q * 4) = v;
            }
        }
        __syncthreads();

        // O += P @ V
        #pragma unroll
        for (int s = 0; s < 8; s++) {
            FragA pa;
            wmma::load_matrix_sync(pa, Ss + (wid * 16) * 72 + s * 8, 72);
            cvt_tf32(pa);
            #pragma unroll
            for (int j = 0; j < 4; j++) {
                FragB vb;
                wmma::load_matrix_sync(vb, Vs + (s * 8) * 72 + j * 16, 72);
                cvt_tf32(vb);
                wmma::mma_sync(oacc[j], pa, vb, oacc[j]);
            }
        }
        __syncthreads();
    }

    rs[tid] = lsum;
    __syncthreads();
    #pragma unroll
    for (int j = 0; j < 4; j++)
        wmma::store_matrix_sync(Ss + (wid * 16) * 72 + j * 16, oacc[j], 72,
                                wmma::mem_row_major);
    __syncthreads();
    {
        int row = tid >> 1;
        float inv = 1.f / (rs[row * 2] + rs[row * 2 + 1]);
        float* pr = Ss + row * 72 + (tid & 1) * 32;
        float* op = g_O + ((size_t)(p * 2 + b) * SEQ + q0 + row) * CD
                  + (size_t)h * 64 + (tid & 1) * 32;
        #pragma unroll
        for (int q = 0; q < 8; q++) {
            float4 v = *(float4*)(pr + q * 4);
            v.x *= inv; v.y *= inv; v.z *= inv; v.w *= inv;
            *(float4*)(op + q * 4) = v;
        }
    }
}

// ---------------------------------------------------------------------------
extern "C" void kernel_launch(void* const* d_in, const int* in_sizes, int n_in,
                              void* d_out, int out_size) {
    const float* x      = (const float*)d_in[0];
    const float* y      = (const float*)d_in[1];
    const float* w_qkv  = (const float*)d_in[2];
    const float* w_proj = (const float*)d_in[3];
    const float* b_proj = (const float*)d_in[4];
    float* out = (float*)d_out;

    cudaFuncSetAttribute(gemm_tc<0>, cudaFuncAttributeMaxDynamicSharedMemorySize, GEMM_SMEM_BYTES);
    cudaFuncSetAttribute(gemm_tc<1>, cudaFuncAttributeMaxDynamicSharedMemorySize, GEMM_SMEM_BYTES);
    cudaFuncSetAttribute(attn_tc,    cudaFuncAttributeMaxDynamicSharedMemorySize, ATT_SMEM_BYTES);

    gemm_tc<0><<<dim3(NQ / 128, RWS / 128), 256, GEMM_SMEM_BYTES>>>(x, y, w_qkv, nullptr, nullptr);
    attn_tc<<<dim3(SEQ / 128, 64), 256, ATT_SMEM_BYTES>>>();
    gemm_tc<1><<<dim3(CD / 128, RWS / 128), 256, GEMM_SMEM_BYTES>>>(x, y, w_proj, b_proj, out);
}

// round 10
// speedup vs baseline: 2.1588x; 2.0643x over previous
#include <cuda_runtime.h>
#include <cuda_fp16.h>
#include <mma.h>
#include <cstdint>
using namespace nvcuda;

#define SEQ 2048
#define CD  1024
#define NQ  3072
#define RWS 8192
#define BR  4096

// scratch (device globals; allocation forbidden)
__device__ __half g_QKVh[(size_t)RWS * NQ];  // fp16 qkv [row, 3C]
__device__ float  g_O[(size_t)RWS * CD];     // fp32 attention out

__device__ __forceinline__ uint32_t smem_u32(const void* p) {
    uint32_t a;
    asm("{ .reg .u64 t; cvta.to.shared.u64 t, %1; cvt.u32.u64 %0, t; }" : "=r"(a) : "l"(p));
    return a;
}
__device__ __forceinline__ float ex2(float x) {
    float r; asm("ex2.approx.f32 %0, %1;" : "=f"(r) : "f"(x)); return r;
}
#define CPA16(dst, src) \
    asm volatile("cp.async.cg.shared.global [%0], [%1], 16;" :: "r"(dst), "l"(src) : "memory")
#define CP_COMMIT() asm volatile("cp.async.commit_group;" ::: "memory")

#define LDSM4(r0, r1, r2, r3, addr)                                         \
    asm volatile("ldmatrix.sync.aligned.m8n8.x4.shared.b16 {%0,%1,%2,%3}, [%4];" \
        : "=r"(r0), "=r"(r1), "=r"(r2), "=r"(r3) : "r"(addr))
#define LDSM4T(r0, r1, r2, r3, addr)                                        \
    asm volatile("ldmatrix.sync.aligned.m8n8.x4.trans.shared.b16 {%0,%1,%2,%3}, [%4];" \
        : "=r"(r0), "=r"(r1), "=r"(r2), "=r"(r3) : "r"(addr))

__device__ __forceinline__ void mma16816(float* d, const uint32_t* a,
                                         const uint32_t* b) {
    asm volatile(
        "mma.sync.aligned.m16n8k16.row.col.f32.f16.f16.f32 "
        "{%0,%1,%2,%3}, {%4,%5,%6,%7}, {%8,%9}, {%0,%1,%2,%3};"
        : "+f"(d[0]), "+f"(d[1]), "+f"(d[2]), "+f"(d[3])
        : "r"(a[0]), "r"(a[1]), "r"(a[2]), "r"(a[3]), "r"(b[0]), "r"(b[1]));
}
__device__ __forceinline__ uint32_t packh2(float lo, float hi) {
    __half2 h = __floats2half2_rn(lo, hi);
    return *(uint32_t*)&h;
}

template<class F>
__device__ __forceinline__ void cvt_tf32(F& f) {
    #pragma unroll
    for (int i = 0; i < f.num_elements; i++) f.x[i] = wmma::__float_to_tf32(f.x[i]);
}
typedef wmma::fragment<wmma::matrix_a, 16, 16, 8, wmma::precision::tf32, wmma::row_major> FragA;
typedef wmma::fragment<wmma::matrix_b, 16, 16, 8, wmma::precision::tf32, wmma::row_major> FragB;
typedef wmma::fragment<wmma::accumulator, 16, 16, 8, float> FragC;

// ---------------------------------------------------------------------------
// GEMM (R5 config: 128 thr, 4 warps 64x64, BK=32, tf32, double-buffered).
// SEL 0: concat(x,y) @ w_qkv -> g_QKVh (fp16).   SEL 1: g_O @ w_proj -> out.
// ---------------------------------------------------------------------------
#define GEMM_SMEM_BYTES 75776
template<int SEL>
__global__ __launch_bounds__(128) void gemm_tc(const float* __restrict__ x,
                                               const float* __restrict__ y,
                                               const float* __restrict__ W,
                                               const float* __restrict__ bias,
                                               float* __restrict__ out) {
    extern __shared__ float sh[];
    const int N = SEL ? CD : NQ;
    const int tid = threadIdx.x, wid = tid >> 5;
    const int bm = blockIdx.y * 128, bn = blockIdx.x * 128;
    const int wr = (wid & 1) * 64, wc = (wid >> 1) * 64;
    const uint32_t sb = smem_u32(sh);

    FragC acc[4][4];
    #pragma unroll
    for (int i = 0; i < 4; i++)
        #pragma unroll
        for (int j = 0; j < 4; j++) wmma::fill_fragment(acc[i][j], 0.f);

    auto issue = [&](int c) {
        int k0 = c * 32;
        uint32_t ab = (uint32_t)(c & 1) * 5120u, bb = 10240u + (uint32_t)(c & 1) * 4352u;
        #pragma unroll
        for (int j = 0; j < 8; j++) {
            int u = tid + j * 128;
            int row = u >> 3, c4 = (u & 7) * 4;
            const float* src;
            int grow = bm + row;
            if (SEL == 0)
                src = ((grow < BR) ? x + (size_t)grow * CD
                                   : y + (size_t)(grow - BR) * CD) + k0 + c4;
            else
                src = g_O + (size_t)grow * CD + k0 + c4;
            CPA16(sb + (ab + (uint32_t)(row * 40 + c4)) * 4u, src);
        }
        #pragma unroll
        for (int j = 0; j < 8; j++) {
            int u = tid + j * 128;
            int row = u >> 5, c4 = (u & 31) * 4;
            CPA16(sb + (bb + (uint32_t)(row * 136 + c4)) * 4u,
                  W + (size_t)(k0 + row) * N + bn + c4);
        }
        CP_COMMIT();
    };

    issue(0);
    for (int c = 0; c < 32; c++) {
        if (c < 31) { issue(c + 1); asm volatile("cp.async.wait_group 1;" ::: "memory"); }
        else        {               asm volatile("cp.async.wait_group 0;" ::: "memory"); }
        __syncthreads();
        const float* A0 = sh + (c & 1) * 5120;
        const float* B0 = sh + 10240 + (c & 1) * 4352;
        #pragma unroll
        for (int s = 0; s < 4; s++) {
            FragA a[4]; FragB b[4];
            #pragma unroll
            for (int i = 0; i < 4; i++) {
                wmma::load_matrix_sync(a[i], A0 + (wr + i * 16) * 40 + s * 8, 40);
                cvt_tf32(a[i]);
            }
            #pragma unroll
            for (int j = 0; j < 4; j++) {
                wmma::load_matrix_sync(b[j], B0 + (s * 8) * 136 + wc + j * 16, 136);
                cvt_tf32(b[j]);
            }
            #pragma unroll
            for (int i = 0; i < 4; i++)
                #pragma unroll
                for (int j = 0; j < 4; j++)
                    wmma::mma_sync(acc[i][j], a[i], b[j], acc[i][j]);
        }
        __syncthreads();
    }

    // epilogue: stage fp32 in smem [128][136], then write
    #pragma unroll
    for (int i = 0; i < 4; i++)
        #pragma unroll
        for (int j = 0; j < 4; j++)
            wmma::store_matrix_sync(sh + (wr + i * 16) * 136 + wc + j * 16,
                                    acc[i][j], 136, wmma::mem_row_major);
    __syncthreads();
    #pragma unroll
    for (int j = 0; j < 32; j++) {
        int u = tid + j * 128;          // f4 unit, 0..4095
        int row = u >> 5, c4 = (u & 31) * 4;
        int grow = bm + row;
        float4 cv = *(float4*)(sh + row * 136 + c4);
        if (SEL == 0) {
            __half2 h0 = __floats2half2_rn(cv.x, cv.y);
            __half2 h1 = __floats2half2_rn(cv.z, cv.w);
            uint2 o;
            o.x = *(uint32_t*)&h0; o.y = *(uint32_t*)&h1;
            *(uint2*)(g_QKVh + (size_t)grow * NQ + bn + c4) = o;
        } else {
            const float* res = ((grow < BR) ? x + (size_t)grow * CD
                                            : y + (size_t)(grow - BR) * CD) + bn + c4;
            float4 bv = *(const float4*)(bias + bn + c4);
            float4 rv = *(const float4*)res;
            cv.x += bv.x + rv.x; cv.y += bv.y + rv.y;
            cv.z += bv.z + rv.z; cv.w += bv.w + rv.w;
            *(float4*)(out + (size_t)grow * CD + bn + c4) = cv;
        }
    }
}

// ---------------------------------------------------------------------------
// Flash attention: raw mma.m16n8k16 fp16, ldmatrix, register softmax (FA2).
// grid (16 q-tiles of 128, 64 jobs), 256 thr (8 warps, 16 q-rows each).
// smem: Qs h[128][72] @0 (18432 B), KV buf b @ 18432+b*18432:
//       K h[64][72] (9216) then V h[64][72] (9216).  Total 55296 B.
// ---------------------------------------------------------------------------
#define ATT_SMEM_BYTES 55296
__global__ __launch_bounds__(256) void attn_fa() {
    extern __shared__ __align__(16) char shc[];
    const uint32_t sb = smem_u32(shc);
    const int tid = threadIdx.x, wid = tid >> 5, lane = tid & 31;

    const int job = blockIdx.y;
    const int p = job >> 5, b = (job >> 4) & 1, h = job & 15;
    const int q0 = blockIdx.x * 128;
    const size_t base  = (size_t)(p * 2 + b) * SEQ * NQ;
    const size_t baseV = (size_t)((1 - p) * 2 + b) * SEQ * NQ;
    const __half* qp = g_QKVh + base + (size_t)h * 64;
    const __half* kp = g_QKVh + base + CD + (size_t)h * 64;
    const __half* vp = g_QKVh + baseV + 2 * CD + (size_t)h * 64;

    auto issueKV = [&](int kt) {
        uint32_t off = 18432u + (uint32_t)(kt & 1) * 18432u;
        #pragma unroll
        for (int j = 0; j < 2; j++) {
            int u = tid + j * 256;          // 0..511
            int r = u >> 3, c8 = (u & 7) * 8;
            size_t go = (size_t)(kt * 64 + r) * NQ + c8;
            uint32_t so = (uint32_t)(r * 72 + c8) * 2u;
            CPA16(sb + off + so, kp + go);
            CPA16(sb + off + 9216u + so, vp + go);
        }
        CP_COMMIT();
    };

    // stage Q + KV(0) as one group
    #pragma unroll
    for (int j = 0; j < 4; j++) {
        int u = tid + j * 256;              // 0..1023
        int r = u >> 3, c8 = (u & 7) * 8;
        CPA16(sb + (uint32_t)(r * 72 + c8) * 2u, qp + (size_t)(q0 + r) * NQ + c8);
    }
    issueKV(0);
    asm volatile("cp.async.wait_group 0;" ::: "memory");
    __syncthreads();

    // Q A-fragments for this warp's 16 rows (held all loop)
    uint32_t qa[4][4];
    #pragma unroll
    for (int c = 0; c < 4; c++) {
        uint32_t addr = sb + (uint32_t)((wid * 16 + (lane & 15)) * 72
                                        + c * 16 + (lane >> 4) * 8) * 2u;
        LDSM4(qa[c][0], qa[c][1], qa[c][2], qa[c][3], addr);
    }

    float o[8][4];
    #pragma unroll
    for (int n = 0; n < 8; n++)
        #pragma unroll
        for (int r = 0; r < 4; r++) o[n][r] = 0.f;
    float l0 = 0.f, l1 = 0.f;
    const float SC = 0.18033688f;           // D^-0.5 * log2(e)

    for (int kt = 0; kt < 32; kt++) {
        if (kt < 31) { issueKV(kt + 1); asm volatile("cp.async.wait_group 1;" ::: "memory"); }
        else         {                  asm volatile("cp.async.wait_group 0;" ::: "memory"); }
        __syncthreads();
        const uint32_t kbase = sb + 18432u + (uint32_t)(kt & 1) * 18432u;
        const uint32_t vbase = kbase + 9216u;

        // S = Q @ K^T  (8 n-tiles of 8 kv, fp32 acc)
        float s[8][4];
        #pragma unroll
        for (int n = 0; n < 8; n++)
            #pragma unroll
            for (int r = 0; r < 4; r++) s[n][r] = 0.f;

        #pragma unroll
        for (int c = 0; c < 4; c++) {       // d chunks of 16 (k dim)
            uint32_t kb[4][4];
            #pragma unroll
            for (int t = 0; t < 4; t++) {   // kv chunks of 16 (2 n-tiles)
                uint32_t addr = kbase + (uint32_t)(
                    (t * 16 + (lane & 7) + (lane >> 4) * 8) * 72
                    + c * 16 + ((lane >> 3) & 1) * 8) * 2u;
                LDSM4(kb[t][0], kb[t][1], kb[t][2], kb[t][3], addr);
            }
            #pragma unroll
            for (int t = 0; t < 4; t++) {
                mma16816(s[t * 2],     qa[c], &kb[t][0]);
                mma16816(s[t * 2 + 1], qa[c], &kb[t][2]);
            }
        }

        // register softmax (max-free): e = exp2(S*SC); quad-reduced row sums
        float rs0 = 0.f, rs1 = 0.f;
        #pragma unroll
        for (int n = 0; n < 8; n++) {
            float e0 = ex2(s[n][0] * SC), e1 = ex2(s[n][1] * SC);
            float e2 = ex2(s[n][2] * SC), e3 = ex2(s[n][3] * SC);
            s[n][0] = e0; s[n][1] = e1; s[n][2] = e2; s[n][3] = e3;
            rs0 += e0 + e1; rs1 += e2 + e3;
        }
        rs0 += __shfl_xor_sync(0xffffffffu, rs0, 1);
        rs0 += __shfl_xor_sync(0xffffffffu, rs0, 2);
        rs1 += __shfl_xor_sync(0xffffffffu, rs1, 1);
        rs1 += __shfl_xor_sync(0xffffffffu, rs1, 2);
        l0 += rs0; l1 += rs1;

        // P acc layout -> A operand (FA2 register pass-through)
        uint32_t pa[4][4];
        #pragma unroll
        for (int c2 = 0; c2 < 4; c2++) {
            pa[c2][0] = packh2(s[c2 * 2][0],     s[c2 * 2][1]);
            pa[c2][1] = packh2(s[c2 * 2][2],     s[c2 * 2][3]);
            pa[c2][2] = packh2(s[c2 * 2 + 1][0], s[c2 * 2 + 1][1]);
            pa[c2][3] = packh2(s[c2 * 2 + 1][2], s[c2 * 2 + 1][3]);
        }

        // O += P @ V   (k = kv chunks of 16; V via ldmatrix.trans)
        #pragma unroll
        for (int c2 = 0; c2 < 4; c2++) {
            #pragma unroll
            for (int j = 0; j < 4; j++) {   // d chunks of 16 (2 n-tiles)
                uint32_t vb[4];
                uint32_t addr = vbase + (uint32_t)(
                    (c2 * 16 + (lane & 7) + ((lane >> 3) & 1) * 8) * 72
                    + j * 16 + (lane >> 4) * 8) * 2u;
                LDSM4T(vb[0], vb[1], vb[2], vb[3], addr);
                mma16816(o[j * 2],     pa[c2], &vb[0]);
                mma16816(o[j * 2 + 1], pa[c2], &vb[2]);
            }
        }
        __syncthreads();   // all warps done with buf (kt&1) before next issue
    }

    // epilogue: normalize rows, write fp32 g_O
    const float inv0 = 1.f / l0, inv1 = 1.f / l1;
    const size_t rbase = (size_t)(p * 2 + b) * SEQ + q0 + wid * 16;
    const size_t r0 = rbase + (lane >> 2), r1 = r0 + 8;
    const int colb = h * 64 + (lane & 3) * 2;
    #pragma unroll
    for (int n = 0; n < 8; n++) {
        float2 v0 = { o[n][0] * inv0, o[n][1] * inv0 };
        float2 v1 = { o[n][2] * inv1, o[n][3] * inv1 };
        *(float2*)(g_O + r0 * CD + colb + n * 8) = v0;
        *(float2*)(g_O + r1 * CD + colb + n * 8) = v1;
    }
}

// ---------------------------------------------------------------------------
extern "C" void kernel_launch(void* const* d_in, const int* in_sizes, int n_in,
                              void* d_out, int out_size) {
    const float* x      = (const float*)d_in[0];
    const float* y      = (const float*)d_in[1];
    const float* w_qkv  = (const float*)d_in[2];
    const float* w_proj = (const float*)d_in[3];
    const float* b_proj = (const float*)d_in[4];
    float* out = (float*)d_out;

    cudaFuncSetAttribute(gemm_tc<0>, cudaFuncAttributeMaxDynamicSharedMemorySize, GEMM_SMEM_BYTES);
    cudaFuncSetAttribute(gemm_tc<1>, cudaFuncAttributeMaxDynamicSharedMemorySize, GEMM_SMEM_BYTES);
    cudaFuncSetAttribute(attn_fa,    cudaFuncAttributeMaxDynamicSharedMemorySize, ATT_SMEM_BYTES);

    gemm_tc<0><<<dim3(NQ / 128, RWS / 128), 128, GEMM_SMEM_BYTES>>>(x, y, w_qkv, nullptr, nullptr);
    attn_fa<<<dim3(SEQ / 128, 64), 256, ATT_SMEM_BYTES>>>();
    gemm_tc<1><<<dim3(CD / 128, RWS / 128), 128, GEMM_SMEM_BYTES>>>(x, y, w_proj, b_proj, out);
}

// round 12
// speedup vs baseline: 5.7627x; 2.6694x over previous
#include <cuda_runtime.h>
#include <cuda_fp16.h>
#include <cstdint>

#define SEQ 2048
#define CD  1024
#define NQ  3072
#define RWS 8192
#define BR  4096

// scratch (device globals; allocation forbidden)
__device__ __half g_Ah [(size_t)RWS * CD];   // fp16 concat(x,y)
__device__ __half g_Wqh[(size_t)CD * NQ];    // fp16 w_qkv [K,N]
__device__ __half g_Wph[(size_t)CD * CD];    // fp16 w_proj [K,N]
__device__ __half g_QKVh[(size_t)RWS * NQ];  // fp16 qkv [row, 3C]
__device__ __half g_Oh [(size_t)RWS * CD];   // fp16 attention out

__device__ __forceinline__ uint32_t smem_u32(const void* p) {
    uint32_t a;
    asm("{ .reg .u64 t; cvta.to.shared.u64 t, %1; cvt.u32.u64 %0, t; }" : "=r"(a) : "l"(p));
    return a;
}
__device__ __forceinline__ float ex2(float x) {
    float r; asm("ex2.approx.f32 %0, %1;" : "=f"(r) : "f"(x)); return r;
}
#define CPA16(dst, src) \
    asm volatile("cp.async.cg.shared.global [%0], [%1], 16;" :: "r"(dst), "l"(src) : "memory")
#define CP_COMMIT() asm volatile("cp.async.commit_group;" ::: "memory")

#define LDSM4(r0, r1, r2, r3, addr)                                         \
    asm volatile("ldmatrix.sync.aligned.m8n8.x4.shared.b16 {%0,%1,%2,%3}, [%4];" \
        : "=r"(r0), "=r"(r1), "=r"(r2), "=r"(r3) : "r"(addr))
#define LDSM4T(r0, r1, r2, r3, addr)                                        \
    asm volatile("ldmatrix.sync.aligned.m8n8.x4.trans.shared.b16 {%0,%1,%2,%3}, [%4];" \
        : "=r"(r0), "=r"(r1), "=r"(r2), "=r"(r3) : "r"(addr))

__device__ __forceinline__ void mma16816(float* d, const uint32_t* a,
                                         const uint32_t* b) {
    asm volatile(
        "mma.sync.aligned.m16n8k16.row.col.f32.f16.f16.f32 "
        "{%0,%1,%2,%3}, {%4,%5,%6,%7}, {%8,%9}, {%0,%1,%2,%3};"
        : "+f"(d[0]), "+f"(d[1]), "+f"(d[2]), "+f"(d[3])
        : "r"(a[0]), "r"(a[1]), "r"(a[2]), "r"(a[3]), "r"(b[0]), "r"(b[1]));
}
__device__ __forceinline__ uint32_t packh2(float lo, float hi) {
    __half2 h = __floats2half2_rn(lo, hi);
    return *(uint32_t*)&h;
}

// ---------------- conversion kernels (device globals referenced IN DEVICE CODE;
// never passed as kernel arguments from host — that was the R7/R11 bug) -------
__global__ __launch_bounds__(256) void conv_A(const float* __restrict__ x,
                                              const float* __restrict__ y) {
    size_t i = ((size_t)blockIdx.x * 256 + threadIdx.x) * 4;
    float4 v = (i < (size_t)BR * CD) ? *(const float4*)(x + i)
                                     : *(const float4*)(y + i - (size_t)BR * CD);
    uint2 o;
    o.x = packh2(v.x, v.y); o.y = packh2(v.z, v.w);
    *(uint2*)(g_Ah + i) = o;
}
template<int SEL>   // 0 -> g_Wqh, 1 -> g_Wph
__global__ __launch_bounds__(256) void conv_W(const float* __restrict__ src) {
    __half* __restrict__ dst = SEL ? g_Wph : g_Wqh;
    size_t i = ((size_t)blockIdx.x * 256 + threadIdx.x) * 4;
    float4 v = *(const float4*)(src + i);
    uint2 o;
    o.x = packh2(v.x, v.y); o.y = packh2(v.z, v.w);
    *(uint2*)(dst + i) = o;
}

// ---------------------------------------------------------------------------
// fp16 GEMM: C[8192, N] = A @ W.  Raw mma.m16n8k16 + ldmatrix.
// 128 thr (4 warps, 64x64 warp tiles), BK=32, double-buffered cp.async.
// SEL 0: g_Ah @ g_Wqh -> g_QKVh (fp16).  SEL 1: g_Oh @ g_Wph -> out (+b+res).
// smem halves: Abuf b at b*5120 (128x40), Bbuf b at 10240+b*4352 (32x136).
// ---------------------------------------------------------------------------
#define GEMM_SMEM_BYTES 37888
template<int SEL>
__global__ __launch_bounds__(128) void gemm_fp16(const float* __restrict__ x,
                                                 const float* __restrict__ y,
                                                 const float* __restrict__ bias,
                                                 float* __restrict__ out) {
    extern __shared__ __half sh[];
    const int N = SEL ? CD : NQ;
    const __half* __restrict__ A = SEL ? g_Oh : g_Ah;
    const __half* __restrict__ W = SEL ? g_Wph : g_Wqh;
    const int tid = threadIdx.x, wid = tid >> 5, lane = tid & 31;
    const int bm = blockIdx.y * 128, bn = blockIdx.x * 128;
    const int wr = (wid & 1) * 64, wc = (wid >> 1) * 64;
    const uint32_t sb = smem_u32(sh);

    float acc[4][8][4];   // m-tile(16) x n-tile(8) x frag
    #pragma unroll
    for (int m = 0; m < 4; m++)
        #pragma unroll
        for (int n = 0; n < 8; n++)
            #pragma unroll
            for (int r = 0; r < 4; r++) acc[m][n][r] = 0.f;

    auto issue = [&](int c) {
        int k0 = c * 32;
        uint32_t ab = (uint32_t)(c & 1) * 5120u, bb = 10240u + (uint32_t)(c & 1) * 4352u;
        #pragma unroll
        for (int j = 0; j < 4; j++) {          // A: 512 16B units
            int u = tid + j * 128;
            int row = u >> 2, c8 = (u & 3) * 8;
            CPA16(sb + (ab + (uint32_t)(row * 40 + c8)) * 2u,
                  A + (size_t)(bm + row) * CD + k0 + c8);
        }
        #pragma unroll
        for (int j = 0; j < 4; j++) {          // B: 512 16B units
            int u = tid + j * 128;
            int row = u >> 4, c8 = (u & 15) * 8;
            CPA16(sb + (bb + (uint32_t)(row * 136 + c8)) * 2u,
                  W + (size_t)(k0 + row) * N + bn + c8);
        }
        CP_COMMIT();
    };

    issue(0);
    for (int c = 0; c < 32; c++) {
        if (c < 31) { issue(c + 1); asm volatile("cp.async.wait_group 1;" ::: "memory"); }
        else        {               asm volatile("cp.async.wait_group 0;" ::: "memory"); }
        __syncthreads();
        const uint32_t abase = sb + (uint32_t)(c & 1) * 10240u;          // bytes
        const uint32_t bbase = sb + 20480u + (uint32_t)(c & 1) * 8704u;  // bytes
        #pragma unroll
        for (int k16 = 0; k16 < 2; k16++) {
            uint32_t a[4][4];
            #pragma unroll
            for (int m = 0; m < 4; m++) {
                uint32_t addr = abase + (uint32_t)(
                    (wr + m * 16 + (lane & 15)) * 40
                    + k16 * 16 + (lane >> 4) * 8) * 2u;
                LDSM4(a[m][0], a[m][1], a[m][2], a[m][3], addr);
            }
            #pragma unroll
            for (int nt = 0; nt < 4; nt++) {   // n chunks of 16
                uint32_t b[4];
                uint32_t addr = bbase + (uint32_t)(
                    (k16 * 16 + (lane & 7) + ((lane >> 3) & 1) * 8) * 136
                    + wc + nt * 16 + (lane >> 4) * 8) * 2u;
                LDSM4T(b[0], b[1], b[2], b[3], addr);
                #pragma unroll
                for (int m = 0; m < 4; m++) {
                    mma16816(acc[m][nt * 2],     a[m], &b[0]);
                    mma16816(acc[m][nt * 2 + 1], a[m], &b[2]);
                }
            }
        }
        __syncthreads();
    }

    // epilogue: direct fragment stores
    const int er = lane >> 2, ec = (lane & 3) * 2;
    #pragma unroll
    for (int m = 0; m < 4; m++) {
        int grow0 = bm + wr + m * 16 + er;
        #pragma unroll
        for (int n = 0; n < 8; n++) {
            int gcol = bn + wc + n * 8 + ec;
            if (SEL == 0) {
                *(uint32_t*)(g_QKVh + (size_t)grow0 * NQ + gcol) =
                    packh2(acc[m][n][0], acc[m][n][1]);
                *(uint32_t*)(g_QKVh + (size_t)(grow0 + 8) * NQ + gcol) =
                    packh2(acc[m][n][2], acc[m][n][3]);
            } else {
                #pragma unroll
                for (int hrow = 0; hrow < 2; hrow++) {
                    int grow = grow0 + hrow * 8;
                    const float* res = ((grow < BR) ? x + (size_t)grow * CD
                                                    : y + (size_t)(grow - BR) * CD) + gcol;
                    float2 rv = *(const float2*)res;
                    float2 bv = *(const float2*)(bias + gcol);
                    float2 o;
                    o.x = acc[m][n][hrow * 2]     + bv.x + rv.x;
                    o.y = acc[m][n][hrow * 2 + 1] + bv.y + rv.y;
                    *(float2*)(out + (size_t)grow * CD + gcol) = o;
                }
            }
        }
    }
}

// ---------------------------------------------------------------------------
// Flash attention (R10 design; fp16 in, fp16 out).
// grid (16 q-tiles of 128, 64 jobs), 256 thr (8 warps, 16 q-rows each).
// smem: Qs h[128][72] @0, KV buf b @ 18432+b*18432 (K then V h[64][72]).
// ---------------------------------------------------------------------------
#define ATT_SMEM_BYTES 55296
__global__ __launch_bounds__(256) void attn_fa() {
    extern __shared__ __align__(16) char shc[];
    const uint32_t sb = smem_u32(shc);
    const int tid = threadIdx.x, wid = tid >> 5, lane = tid & 31;

    const int job = blockIdx.y;
    const int p = job >> 5, b = (job >> 4) & 1, h = job & 15;
    const int q0 = blockIdx.x * 128;
    const size_t base  = (size_t)(p * 2 + b) * SEQ * NQ;
    const size_t baseV = (size_t)((1 - p) * 2 + b) * SEQ * NQ;
    const __half* qp = g_QKVh + base + (size_t)h * 64;
    const __half* kp = g_QKVh + base + CD + (size_t)h * 64;
    const __half* vp = g_QKVh + baseV + 2 * CD + (size_t)h * 64;

    auto issueKV = [&](int kt) {
        uint32_t off = 18432u + (uint32_t)(kt & 1) * 18432u;
        #pragma unroll
        for (int j = 0; j < 2; j++) {
            int u = tid + j * 256;
            int r = u >> 3, c8 = (u & 7) * 8;
            size_t go = (size_t)(kt * 64 + r) * NQ + c8;
            uint32_t so = (uint32_t)(r * 72 + c8) * 2u;
            CPA16(sb + off + so, kp + go);
            CPA16(sb + off + 9216u + so, vp + go);
        }
        CP_COMMIT();
    };

    #pragma unroll
    for (int j = 0; j < 4; j++) {
        int u = tid + j * 256;
        int r = u >> 3, c8 = (u & 7) * 8;
        CPA16(sb + (uint32_t)(r * 72 + c8) * 2u, qp + (size_t)(q0 + r) * NQ + c8);
    }
    issueKV(0);
    asm volatile("cp.async.wait_group 0;" ::: "memory");
    __syncthreads();

    uint32_t qa[4][4];
    #pragma unroll
    for (int c = 0; c < 4; c++) {
        uint32_t addr = sb + (uint32_t)((wid * 16 + (lane & 15)) * 72
                                        + c * 16 + (lane >> 4) * 8) * 2u;
        LDSM4(qa[c][0], qa[c][1], qa[c][2], qa[c][3], addr);
    }

    float o[8][4];
    #pragma unroll
    for (int n = 0; n < 8; n++)
        #pragma unroll
        for (int r = 0; r < 4; r++) o[n][r] = 0.f;
    float l0 = 0.f, l1 = 0.f;
    const float SC = 0.18033688f;           // D^-0.5 * log2(e)

    for (int kt = 0; kt < 32; kt++) {
        if (kt < 31) { issueKV(kt + 1); asm volatile("cp.async.wait_group 1;" ::: "memory"); }
        else         {                  asm volatile("cp.async.wait_group 0;" ::: "memory"); }
        __syncthreads();
        const uint32_t kbase = sb + 18432u + (uint32_t)(kt & 1) * 18432u;
        const uint32_t vbase = kbase + 9216u;

        float s[8][4];
        #pragma unroll
        for (int n = 0; n < 8; n++)
            #pragma unroll
            for (int r = 0; r < 4; r++) s[n][r] = 0.f;

        #pragma unroll
        for (int c = 0; c < 4; c++) {
            uint32_t kb[4][4];
            #pragma unroll
            for (int t = 0; t < 4; t++) {
                uint32_t addr = kbase + (uint32_t)(
                    (t * 16 + (lane & 7) + (lane >> 4) * 8) * 72
                    + c * 16 + ((lane >> 3) & 1) * 8) * 2u;
                LDSM4(kb[t][0], kb[t][1], kb[t][2], kb[t][3], addr);
            }
            #pragma unroll
            for (int t = 0; t < 4; t++) {
                mma16816(s[t * 2],     qa[c], &kb[t][0]);
                mma16816(s[t * 2 + 1], qa[c], &kb[t][2]);
            }
        }

        float rs0 = 0.f, rs1 = 0.f;
        #pragma unroll
        for (int n = 0; n < 8; n++) {
            float e0 = ex2(s[n][0] * SC), e1 = ex2(s[n][1] * SC);
            float e2 = ex2(s[n][2] * SC), e3 = ex2(s[n][3] * SC);
            s[n][0] = e0; s[n][1] = e1; s[n][2] = e2; s[n][3] = e3;
            rs0 += e0 + e1; rs1 += e2 + e3;
        }
        rs0 += __shfl_xor_sync(0xffffffffu, rs0, 1);
        rs0 += __shfl_xor_sync(0xffffffffu, rs0, 2);
        rs1 += __shfl_xor_sync(0xffffffffu, rs1, 1);
        rs1 += __shfl_xor_sync(0xffffffffu, rs1, 2);
        l0 += rs0; l1 += rs1;

        uint32_t pa[4][4];
        #pragma unroll
        for (int c2 = 0; c2 < 4; c2++) {
            pa[c2][0] = packh2(s[c2 * 2][0],     s[c2 * 2][1]);
            pa[c2][1] = packh2(s[c2 * 2][2],     s[c2 * 2][3]);
            pa[c2][2] = packh2(s[c2 * 2 + 1][0], s[c2 * 2 + 1][1]);
            pa[c2][3] = packh2(s[c2 * 2 + 1][2], s[c2 * 2 + 1][3]);
        }

        #pragma unroll
        for (int c2 = 0; c2 < 4; c2++) {
            #pragma unroll
            for (int j = 0; j < 4; j++) {
                uint32_t vb[4];
                uint32_t addr = vbase + (uint32_t)(
                    (c2 * 16 + (lane & 7) + ((lane >> 3) & 1) * 8) * 72
                    + j * 16 + (lane >> 4) * 8) * 2u;
                LDSM4T(vb[0], vb[1], vb[2], vb[3], addr);
                mma16816(o[j * 2],     pa[c2], &vb[0]);
                mma16816(o[j * 2 + 1], pa[c2], &vb[2]);
            }
        }
        __syncthreads();
    }

    // epilogue: normalize, write fp16 g_Oh
    const float inv0 = 1.f / l0, inv1 = 1.f / l1;
    const size_t rbase = (size_t)(p * 2 + b) * SEQ + q0 + wid * 16;
    const size_t r0 = rbase + (lane >> 2), r1 = r0 + 8;
    const int colb = h * 64 + (lane & 3) * 2;
    #pragma unroll
    for (int n = 0; n < 8; n++) {
        *(uint32_t*)(g_Oh + r0 * CD + colb + n * 8) =
            packh2(o[n][0] * inv0, o[n][1] * inv0);
        *(uint32_t*)(g_Oh + r1 * CD + colb + n * 8) =
            packh2(o[n][2] * inv1, o[n][3] * inv1);
    }
}

// ---------------------------------------------------------------------------
extern "C" void kernel_launch(void* const* d_in, const int* in_sizes, int n_in,
                              void* d_out, int out_size) {
    const float* x      = (const float*)d_in[0];
    const float* y      = (const float*)d_in[1];
    const float* w_qkv  = (const float*)d_in[2];
    const float* w_proj = (const float*)d_in[3];
    const float* b_proj = (const float*)d_in[4];
    float* out = (float*)d_out;

    cudaFuncSetAttribute(gemm_fp16<0>, cudaFuncAttributeMaxDynamicSharedMemorySize, GEMM_SMEM_BYTES);
    cudaFuncSetAttribute(gemm_fp16<1>, cudaFuncAttributeMaxDynamicSharedMemorySize, GEMM_SMEM_BYTES);
    cudaFuncSetAttribute(attn_fa,      cudaFuncAttributeMaxDynamicSharedMemorySize, ATT_SMEM_BYTES);

    conv_A<<<(RWS * CD) / 1024, 256>>>(x, y);
    conv_W<0><<<(CD * NQ) / 1024, 256>>>(w_qkv);
    conv_W<1><<<(CD * CD) / 1024, 256>>>(w_proj);

    gemm_fp16<0><<<dim3(NQ / 128, RWS / 128), 128, GEMM_SMEM_BYTES>>>(x, y, nullptr, nullptr);
    attn_fa<<<dim3(SEQ / 128, 64), 256, ATT_SMEM_BYTES>>>();
    gemm_fp16<1><<<dim3(CD / 128, RWS / 128), 128, GEMM_SMEM_BYTES>>>(x, y, b_proj, out);
}